// round 16
// baseline (speedup 1.0000x reference)
#include <cuda_runtime.h>
#include <cuda_fp16.h>
#include <cstdint>

#define BB   8
#define TT   2048
#define CIN  1024
#define HD   128
#define BT   (BB*TT)          // 16384 rows

typedef unsigned int u32;

// ---------------------------------------------------------------------------
// Device scratch (static globals: allocation-guard safe). fp16.
// ---------------------------------------------------------------------------
__device__ __align__(256) __half gQ[(size_t)BT * HD];
__device__ __align__(256) __half gK[(size_t)BT * HD];
__device__ __align__(256) __half gV[(size_t)BT * HD];
__device__ __align__(256) __half gWc[3 * CIN * HD];   // fp16 W, [o][k][n]

// ---------------------------------------------------------------------------
// Helpers
// ---------------------------------------------------------------------------
__device__ __forceinline__ u32 pack_half2(float x, float y) {
    __half2 h = __floats2half2_rn(x, y);
    return *reinterpret_cast<u32*>(&h);
}
__device__ __forceinline__ void mma_f16(float* d, const u32* a, u32 b0, u32 b1) {
    asm volatile(
        "mma.sync.aligned.m16n8k16.row.col.f32.f16.f16.f32 "
        "{%0,%1,%2,%3}, {%4,%5,%6,%7}, {%8,%9}, {%0,%1,%2,%3};"
        : "+f"(d[0]), "+f"(d[1]), "+f"(d[2]), "+f"(d[3])
        : "r"(a[0]), "r"(a[1]), "r"(a[2]), "r"(a[3]), "r"(b0), "r"(b1));
}
__device__ __forceinline__ u32 smem_u32(const void* p) {
    u32 a;
    asm("{ .reg .u64 t; cvta.to.shared.u64 t, %1; cvt.u32.u64 %0, t; }"
        : "=r"(a) : "l"(p));
    return a;
}
__device__ __forceinline__ void ldsm4(u32 a, u32& r0, u32& r1, u32& r2, u32& r3) {
    asm volatile("ldmatrix.sync.aligned.m8n8.x4.shared.b16 {%0,%1,%2,%3}, [%4];"
                 : "=r"(r0), "=r"(r1), "=r"(r2), "=r"(r3) : "r"(a));
}
__device__ __forceinline__ void ldsm4t(u32 a, u32& r0, u32& r1, u32& r2, u32& r3) {
    asm volatile("ldmatrix.sync.aligned.m8n8.x4.trans.shared.b16 {%0,%1,%2,%3}, [%4];"
                 : "=r"(r0), "=r"(r1), "=r"(r2), "=r"(r3) : "r"(a));
}
#define CP16(dst, src) \
    asm volatile("cp.async.cg.shared.global [%0], [%1], 16;" \
                 :: "r"(dst), "l"(src) : "memory")
#define CP_COMMIT() asm volatile("cp.async.commit_group;" ::: "memory")
#define CP_WAIT(n)  asm volatile("cp.async.wait_group %0;" :: "n"(n) : "memory")
#define BAR_GRP(id) asm volatile("bar.sync %0, 128;" :: "r"(id) : "memory")

// ---------------------------------------------------------------------------
// Kernel A: elementwise W fp32 -> fp16, [o][k][n] (no transpose; 8 elems/thr).
// ---------------------------------------------------------------------------
__global__ __launch_bounds__(256) void convert_w(const float* __restrict__ Wq,
                                                 const float* __restrict__ Wk,
                                                 const float* __restrict__ Wv)
{
    const size_t base = ((size_t)blockIdx.x * 256 + threadIdx.x) * 8;
    const int o = (int)(base >> 17);
    const int r = (int)(base & 131071);
    const float* W = (o == 0) ? Wq : (o == 1 ? Wk : Wv);
    float4 a = *reinterpret_cast<const float4*>(W + r);
    float4 b = *reinterpret_cast<const float4*>(W + r + 4);
    uint4 v;
    v.x = pack_half2(a.x, a.y); v.y = pack_half2(a.z, a.w);
    v.z = pack_half2(b.x, b.y); v.w = pack_half2(b.z, b.w);
    *reinterpret_cast<uint4*>(gWc + (size_t)o * (CIN * HD) + r) = v;
}

// ---------------------------------------------------------------------------
// Kernel B: FUSED QKV GEMM — one CTA computes Q,K,V (N=384) for 64 M-rows.
// BM=64, BK=32; 8 warps = 2 wm x 4 wh (warp: 32 m-rows x 96 n-cols).
// X: fp32 LDG reg-prefetch -> fp16 smem [m][k] DOUBLE-BUFFERED.
// W: fp16 cp.async THREE-STAGE ring (prefetch distance 2 MMA phases),
//    issued AFTER the barrier -> ONE __syncthreads per K-iteration.
// __launch_bounds__(256, 2): 2 CTAs/SM -> 256 CTAs = 1 wave.
// ---------------------------------------------------------------------------
#define GS   40                           // X smem k-stride (halves)
#define XSTG (64 * GS)                    // halves per X stage
#define WST2 392                          // W smem n-stride (halves), 784 B
#define WSTG (32 * WST2)                  // halves per W stage
#define GEMM_SMEM ((2 * XSTG + 3 * WSTG) * 2)

__global__ __launch_bounds__(256, 2) void qkv_mma(const float* __restrict__ X)
{
    extern __shared__ __half smg[];
    const u32 Xs_b = smem_u32(smg);                   // 2 stages [64][GS]
    const u32 Ws_b = smem_u32(smg + 2 * XSTG);        // 3 stages [32][WST2]

    const int t    = threadIdx.x;
    const int lane = t & 31;
    const int wrp  = t >> 5;
    const int wm   = wrp & 1;             // m-group: rows wm*32..+31
    const int wh   = wrp >> 1;            // n-quarter: cols wh*96..+95
    const int g    = lane >> 2;
    const int qd   = (lane & 3) << 1;
    const int j    = lane >> 3;
    const int lr   = lane & 7;
    const size_t m0 = (size_t)blockIdx.x * 64;

    u32 ga_off[2];
    #pragma unroll
    for (int mf = 0; mf < 2; mf++)
        ga_off[mf] = (wm * 32 + mf * 16 + ((j & 1) << 3) + lr) * 80 + ((j >> 1) << 4);
    const u32 bT_off = (((j & 1) << 3) + lr) * 784 + ((j >> 1) << 4) + wh * 192;

    float acc[2][12][4];
    #pragma unroll
    for (int mf = 0; mf < 2; mf++)
        #pragma unroll
        for (int nf = 0; nf < 12; nf++)
            #pragma unroll
            for (int e = 0; e < 4; e++) acc[mf][nf][e] = 0.f;

    float4 xv[2];
    const int xr = t >> 3;                // X row base (0..31)
    const int xc = (t & 7) << 2;          // X col (floats)
    const int wk0 = t >> 4, wn0 = t & 15; // W cp.async indices

    // ---- prologue: X(0) into regs, W(0) and W(1) into stages 0,1 ----
    #pragma unroll
    for (int i = 0; i < 2; i++)
        xv[i] = *reinterpret_cast<const float4*>(X + (m0 + xr + i * 32) * CIN + xc);
    #pragma unroll
    for (int st = 0; st < 2; st++) {
        #pragma unroll
        for (int o = 0; o < 3; o++)
            #pragma unroll
            for (int jj = 0; jj < 2; jj++) {
                const int k = wk0 + jj * 16;
                CP16(Ws_b + (u32)st * (WSTG * 2) + k * 784 + o * 256 + wn0 * 16,
                     gWc + (size_t)o * (CIN * HD) + (size_t)(st * 32 + k) * HD + wn0 * 8);
            }
        CP_COMMIT();
    }

    for (int it = 0; it < 32; it++) {
        // store X(it) into stage it&1 (stage last read at MMA(it-2); all warps
        // passed barrier(it-1) which follows MMA(it-2) -> safe)
        __half* Xst = smg + (it & 1) * XSTG;
        #pragma unroll
        for (int i = 0; i < 2; i++) {
            const int r = xr + i * 32;
            *reinterpret_cast<u32*>(&Xst[r * GS + xc])     = pack_half2(xv[i].x, xv[i].y);
            *reinterpret_cast<u32*>(&Xst[r * GS + xc + 2]) = pack_half2(xv[i].z, xv[i].w);
        }
        if (it < 31) {
            const int k1 = (it + 1) * 32;
            #pragma unroll
            for (int i = 0; i < 2; i++)
                xv[i] = *reinterpret_cast<const float4*>(X + (m0 + xr + i * 32) * CIN + k1 + xc);
        }

        CP_WAIT(1);                       // W(it) done (W(it+1) may be in flight)
        __syncthreads();                  // X(it) + W(it) visible CTA-wide

        // issue W(it+2) into stage (it+2)%3 (last read at MMA(it-1): safe)
        if (it < 30) {
            const int k2 = (it + 2) * 32;
            const u32 dstb = Ws_b + (u32)((it + 2) % 3) * (WSTG * 2);
            #pragma unroll
            for (int o = 0; o < 3; o++)
                #pragma unroll
                for (int jj = 0; jj < 2; jj++) {
                    const int k = wk0 + jj * 16;
                    CP16(dstb + k * 784 + o * 256 + wn0 * 16,
                         gWc + (size_t)o * (CIN * HD) + (size_t)(k2 + k) * HD + wn0 * 8);
                }
        }
        CP_COMMIT();                      // empty group keeps wait cadence uniform

        const u32 xb = Xs_b + (it & 1) * (XSTG * 2);
        const u32 wb = Ws_b + (u32)(it % 3) * (WSTG * 2);
        #pragma unroll
        for (int ks = 0; ks < 2; ks++) {
            u32 ah[2][4];
            #pragma unroll
            for (int mf = 0; mf < 2; mf++)
                ldsm4(xb + ga_off[mf] + ks * 32, ah[mf][0], ah[mf][1], ah[mf][2], ah[mf][3]);
            #pragma unroll
            for (int nf2 = 0; nf2 < 6; nf2++) {
                u32 b0, b1, b2, b3;
                ldsm4t(wb + bT_off + ks * (16 * 784) + nf2 * 32, b0, b1, b2, b3);
                #pragma unroll
                for (int mf = 0; mf < 2; mf++) {
                    mma_f16(acc[mf][2 * nf2],     ah[mf], b0, b1);
                    mma_f16(acc[mf][2 * nf2 + 1], ah[mf], b2, b3);
                }
            }
        }
    }

    // Epilogue: route each n-frag to its output (Q scaled by 1/32), fp16 stores
    #pragma unroll
    for (int mf = 0; mf < 2; mf++) {
        const size_t r = m0 + wm * 32 + mf * 16 + g;
        #pragma unroll
        for (int nf = 0; nf < 12; nf++) {
            const int gn  = wh * 96 + nf * 8 + qd;
            const int o   = gn >> 7;
            const int col = gn & 127;
            const float sc = (o == 0) ? 0.03125f : 1.0f;
            __half* G = (o == 0) ? gQ : (o == 1 ? gK : gV);
            *reinterpret_cast<u32*>(&G[r * HD + col]) =
                pack_half2(acc[mf][nf][0] * sc, acc[mf][nf][1] * sc);
            *reinterpret_cast<u32*>(&G[(r + 8) * HD + col]) =
                pack_half2(acc[mf][nf][2] * sc, acc[mf][nf][3] * sc);
        }
    }
}

// ---------------------------------------------------------------------------
// Kernel C: causal flash attention, PAIRED grid + split-KV warp groups.
// NEW: K and V both double-buffered per group; ONE commit group {K(i+1),V(i+1)}
// per iter -> ONE CP_WAIT + ONE BAR_GRP per iter (PV needs no wait/barrier:
// V(i) was covered by the top-of-iter wait; V(i+1) writes target the stage
// last read at PV(i-1), ordered by this iter's barrier).
// ---------------------------------------------------------------------------
#define AST 136                      // smem row stride in halves (272 B)
#define TILE_B (64 * AST * 2)        // one 64x128 fp16 tile: 17408 B
#define ATTN_SMEM (8 * TILE_B)       // per group: K0 K1 V0 V1 -> 139264 B

__device__ __forceinline__ void cp_tile64(u32 dst, const __half* src, int tg)
{
    #pragma unroll
    for (int i = 0; i < 8; i++) {         // 128 threads x 8 = 1024 chunks of 16B
        const int c   = tg + i * 128;
        const int row = c >> 4;           // 0..63
        const int col = c & 15;
        CP16(dst + row * 272 + col * 16, src + row * 128 + col * 8);
    }
}

__global__ __launch_bounds__(256) void attn_kernel(float* __restrict__ out)
{
    extern __shared__ __half sma[];
    const u32 base = smem_u32(sma);

    const int t    = threadIdx.x;
    const int lane = t & 31;
    const int warp = t >> 5;
    const int wg   = warp >> 2;           // 0 = group A (even jt), 1 = B (odd jt)
    const int w4   = warp & 3;            // warp within group -> q-rows w4*16..+15
    const int tg   = t & 127;             // thread id within group
    const int g    = lane >> 2;
    const int qd   = (lane & 3) << 1;
    const int j    = lane >> 3;
    const int lr   = lane & 7;
    const int b    = blockIdx.y;

    const u32 gbase = base + (u32)wg * 4 * TILE_B;
    const u32 K_s0 = gbase,              K_s1 = gbase + TILE_B;
    const u32 V_s0 = gbase + 2 * TILE_B, V_s1 = gbase + 3 * TILE_B;

    const u32 a_off  = (w4 * 16 + ((j & 1) << 3) + lr) * 272 + ((j >> 1) << 4);
    const u32 kb_off = (((j >> 1) << 3) + lr) * 272 + ((j & 1) << 4);
    const u32 vb_off = (((j & 1) << 3) + lr) * 272 + ((j >> 1) << 4);

    #pragma unroll 1
    for (int half = 0; half < 2; half++) {
        const int qt = (half == 0) ? (31 - (int)blockIdx.x) : (int)blockIdx.x;
        const int i0 = qt * 64;
        const int n_g = (qt >= wg) ? (((qt - wg) >> 1) + 1) : 0;

        float O[16][4];
        #pragma unroll
        for (int nf = 0; nf < 16; nf++)
            #pragma unroll
            for (int e = 0; e < 4; e++) O[nf][e] = 0.f;
        float mrow[2] = {-1e30f, -1e30f};
        float lrow[2] = {0.f, 0.f};

        if (n_g > 0) {
            // ---- prologue: K(0)->K_s0, V(0)->V_s0, Q staged through K_s1 ----
            cp_tile64(K_s0, gK + ((size_t)b * TT + wg * 64) * HD, tg);
            cp_tile64(V_s0, gV + ((size_t)b * TT + wg * 64) * HD, tg);
            cp_tile64(K_s1, gQ + ((size_t)b * TT + i0) * HD, tg);
            CP_COMMIT();
            CP_WAIT(0);
            BAR_GRP(wg + 1);

            u32 qh[8][4];
            #pragma unroll
            for (int ks = 0; ks < 8; ks++)
                ldsm4(K_s1 + a_off + ks * 32, qh[ks][0], qh[ks][1], qh[ks][2], qh[ks][3]);
            BAR_GRP(wg + 1);             // Q frags extracted before K(1) overwrites K_s1

            for (int i = 0; i < n_g; i++) {
                const int jt = wg + 2 * i;
                const int stage = i & 1;
                const u32 kh = stage ? K_s1 : K_s0;
                const u32 vh = stage ? V_s1 : V_s0;

                CP_WAIT(0);              // group(i-1) = {K(i), V(i)} complete
                BAR_GRP(wg + 1);         // visible group-wide; all past PV(i-1)

                // prefetch {K(i+1), V(i+1)} into the other stages
                if (i + 1 < n_g) {
                    const size_t roff = ((size_t)b * TT + (jt + 2) * 64) * HD;
                    cp_tile64(stage ? K_s0 : K_s1, gK + roff, tg);
                    cp_tile64(stage ? V_s0 : V_s1, gV + roff, tg);
                }
                CP_COMMIT();             // empty group keeps cadence uniform

                // ---- S = Q K^T ----
                float s[8][4];
                #pragma unroll
                for (int nf = 0; nf < 8; nf++)
                    #pragma unroll
                    for (int e = 0; e < 4; e++) s[nf][e] = 0.f;

                #pragma unroll
                for (int ks = 0; ks < 8; ks++) {
                    #pragma unroll
                    for (int nf2 = 0; nf2 < 4; nf2++) {
                        u32 b0, b1, b2, b3;
                        ldsm4(kh + kb_off + nf2 * (16 * 272) + ks * 32, b0, b1, b2, b3);
                        mma_f16(s[2 * nf2],     qh[ks], b0, b1);
                        mma_f16(s[2 * nf2 + 1], qh[ks], b2, b3);
                    }
                }

                // ---- causal mask on diagonal tile ----
                if (jt == qt) {
                    #pragma unroll
                    for (int nf = 0; nf < 8; nf++) {
                        const int c0 = nf * 8 + qd;
                        const int r0 = w4 * 16 + g;
                        if (c0     > r0)     s[nf][0] = -1e30f;
                        if (c0 + 1 > r0)     s[nf][1] = -1e30f;
                        if (c0     > r0 + 8) s[nf][2] = -1e30f;
                        if (c0 + 1 > r0 + 8) s[nf][3] = -1e30f;
                    }
                }

                // ---- online softmax ----
                float mx0 = -1e30f, mx1 = -1e30f;
                #pragma unroll
                for (int nf = 0; nf < 8; nf++) {
                    mx0 = fmaxf(mx0, fmaxf(s[nf][0], s[nf][1]));
                    mx1 = fmaxf(mx1, fmaxf(s[nf][2], s[nf][3]));
                }
                mx0 = fmaxf(mx0, __shfl_xor_sync(0xffffffffu, mx0, 1));
                mx0 = fmaxf(mx0, __shfl_xor_sync(0xffffffffu, mx0, 2));
                mx1 = fmaxf(mx1, __shfl_xor_sync(0xffffffffu, mx1, 1));
                mx1 = fmaxf(mx1, __shfl_xor_sync(0xffffffffu, mx1, 2));
                const float mn0 = fmaxf(mrow[0], mx0);
                const float mn1 = fmaxf(mrow[1], mx1);
                const float a0  = __expf(mrow[0] - mn0);
                const float a1  = __expf(mrow[1] - mn1);
                mrow[0] = mn0; mrow[1] = mn1;

                float sum0 = 0.f, sum1 = 0.f;
                #pragma unroll
                for (int nf = 0; nf < 8; nf++) {
                    s[nf][0] = __expf(s[nf][0] - mn0);
                    s[nf][1] = __expf(s[nf][1] - mn0);
                    s[nf][2] = __expf(s[nf][2] - mn1);
                    s[nf][3] = __expf(s[nf][3] - mn1);
                    sum0 += s[nf][0] + s[nf][1];
                    sum1 += s[nf][2] + s[nf][3];
                }
                sum0 += __shfl_xor_sync(0xffffffffu, sum0, 1);
                sum0 += __shfl_xor_sync(0xffffffffu, sum0, 2);
                sum1 += __shfl_xor_sync(0xffffffffu, sum1, 1);
                sum1 += __shfl_xor_sync(0xffffffffu, sum1, 2);
                lrow[0] = lrow[0] * a0 + sum0;
                lrow[1] = lrow[1] * a1 + sum1;

                #pragma unroll
                for (int nf = 0; nf < 16; nf++) {
                    O[nf][0] *= a0; O[nf][1] *= a0;
                    O[nf][2] *= a1; O[nf][3] *= a1;
                }

                // ---- O += P V : no wait/barrier needed (V(i) covered above) ----
                #pragma unroll
                for (int ks = 0; ks < 4; ks++) {
                    u32 ph[4];
                    ph[0] = pack_half2(s[2 * ks][0],     s[2 * ks][1]);
                    ph[1] = pack_half2(s[2 * ks][2],     s[2 * ks][3]);
                    ph[2] = pack_half2(s[2 * ks + 1][0], s[2 * ks + 1][1]);
                    ph[3] = pack_half2(s[2 * ks + 1][2], s[2 * ks + 1][3]);
                    #pragma unroll
                    for (int nf2 = 0; nf2 < 8; nf2++) {
                        u32 b0, b1, b2, b3;
                        ldsm4t(vh + vb_off + ks * (16 * 272) + nf2 * 32, b0, b1, b2, b3);
                        mma_f16(O[2 * nf2],     ph, b0, b1);
                        mma_f16(O[2 * nf2 + 1], ph, b2, b3);
                    }
                }
            }
            CP_WAIT(0);
        }

        // ---- merge group B partials into A, then A stores ----
        float* ex = reinterpret_cast<float*>(reinterpret_cast<char*>(sma) + 4 * TILE_B);
        if (wg == 1) {
            float* p = ex + tg * 68;
            #pragma unroll
            for (int nf = 0; nf < 16; nf++) {
                p[nf * 4 + 0] = O[nf][0]; p[nf * 4 + 1] = O[nf][1];
                p[nf * 4 + 2] = O[nf][2]; p[nf * 4 + 3] = O[nf][3];
            }
            p[64] = mrow[0]; p[65] = mrow[1];
            p[66] = lrow[0]; p[67] = lrow[1];
        }
        __syncthreads();
        if (wg == 0) {
            const float* p = ex + tg * 68;
            const float mB0 = p[64], mB1 = p[65], lB0 = p[66], lB1 = p[67];
            const float m0 = fmaxf(mrow[0], mB0);
            const float m1 = fmaxf(mrow[1], mB1);
            const float aA0 = __expf(mrow[0] - m0), aB0 = __expf(mB0 - m0);
            const float aA1 = __expf(mrow[1] - m1), aB1 = __expf(mB1 - m1);
            const float inv0 = 1.0f / (lrow[0] * aA0 + lB0 * aB0);
            const float inv1 = 1.0f / (lrow[1] * aA1 + lB1 * aB1);
            const size_t r0 = (size_t)b * TT + i0 + w4 * 16 + g;
            #pragma unroll
            for (int nf = 0; nf < 16; nf++) {
                const int col = nf * 8 + qd;
                float2 v0 = make_float2(
                    (O[nf][0] * aA0 + p[nf * 4 + 0] * aB0) * inv0,
                    (O[nf][1] * aA0 + p[nf * 4 + 1] * aB0) * inv0);
                float2 v1 = make_float2(
                    (O[nf][2] * aA1 + p[nf * 4 + 2] * aB1) * inv1,
                    (O[nf][3] * aA1 + p[nf * 4 + 3] * aB1) * inv1);
                *reinterpret_cast<float2*>(out + r0 * HD + col)       = v0;
                *reinterpret_cast<float2*>(out + (r0 + 8) * HD + col) = v1;
            }
        }
        __syncthreads();     // protect exchange area before next half's prologue
    }
}

// ---------------------------------------------------------------------------
extern "C" void kernel_launch(void* const* d_in, const int* in_sizes, int n_in,
                              void* d_out, int out_size)
{
    const float* X  = (const float*)d_in[0];   // [8,2048,1024]
    const float* Wq = (const float*)d_in[1];   // [1024,128]
    const float* Wk = (const float*)d_in[2];
    const float* Wv = (const float*)d_in[3];
    float* out = (float*)d_out;                // [8,2048,128]
    (void)in_sizes; (void)n_in; (void)out_size;

    cudaFuncSetAttribute(qkv_mma,
        cudaFuncAttributeMaxDynamicSharedMemorySize, GEMM_SMEM);
    cudaFuncSetAttribute(attn_kernel,
        cudaFuncAttributeMaxDynamicSharedMemorySize, ATTN_SMEM);

    convert_w<<<3 * CIN * HD / (256 * 8), 256>>>(Wq, Wk, Wv);
    qkv_mma<<<BT / 64, 256, GEMM_SMEM>>>(X);
    attn_kernel<<<dim3(16, BB), 256, ATTN_SMEM>>>(out);
}